// round 16
// baseline (speedup 1.0000x reference)
#include <cuda_runtime.h>
#include <cuda_fp16.h>
#include <math.h>
#include <stdint.h>

#define N_NODES 20000
#define N_EDGES 320000
#define FS      1000
#define XCOLS   1005
#define F1      512
#define F2      256
#define F3      64
#define KP1     1024             // padded resnet K

// ======================= static scratch =======================
__device__ __half g_A2 [(size_t)N_NODES * KP1];
__device__ __half g_h2s[(size_t)N_NODES * F1];   // layer-1 activations (GEMM2 input)
__device__ __half g_h3s[(size_t)N_NODES * F2];   // layer-2 activations (GEMM3 input)
__device__ __half g_W1T[(size_t)F1 * KP1];
__device__ __half g_W2T[(size_t)F2 * F1];
__device__ __half g_W3T[(size_t)F3 * F2];
__device__ __half g_base[(size_t)N_NODES * F1];  // fp16 table contribution
__device__ float g_t   [(size_t)N_NODES * F1];
__device__ float g_dinv[N_NODES];
__device__ float g_preL[3 * F1];
__device__ float g_preR[11 * F1];
__device__ float g_preC[3 * 256 * F1];
__device__ int   g_degi[N_NODES];
__device__ int   g_rp[N_NODES + 1];
__device__ int   g_cursor[N_NODES];
__device__ int2  g_edge[N_EDGES];

// ======================= PTX helpers =======================
__device__ __forceinline__ uint32_t smem_u32(const void* p) {
    uint32_t a;
    asm("{ .reg .u64 t; cvta.to.shared.u64 t, %1; cvt.u32.u64 %0, t; }" : "=r"(a) : "l"(p));
    return a;
}
__device__ __forceinline__ void cp16(uint32_t dst, const void* src, bool pred) {
    int sz = pred ? 16 : 0;
    asm volatile("cp.async.cg.shared.global [%0], [%1], 16, %2;"
                 :: "r"(dst), "l"(src), "r"(sz) : "memory");
}
#define CP_COMMIT() asm volatile("cp.async.commit_group;" ::: "memory")
#define CP_WAIT2()  asm volatile("cp.async.wait_group 2;" ::: "memory")

__device__ __forceinline__ void ldsm_x4(uint32_t* r, uint32_t addr) {
    asm volatile("ldmatrix.sync.aligned.m8n8.x4.shared.b16 {%0,%1,%2,%3}, [%4];"
                 : "=r"(r[0]), "=r"(r[1]), "=r"(r[2]), "=r"(r[3]) : "r"(addr));
}
__device__ __forceinline__ void mma_f16(float* d, const uint32_t* a, const uint32_t* b) {
    asm volatile("mma.sync.aligned.m16n8k16.row.col.f32.f16.f16.f32 "
                 "{%0,%1,%2,%3}, {%4,%5,%6,%7}, {%8,%9}, {%0,%1,%2,%3};"
                 : "+f"(d[0]), "+f"(d[1]), "+f"(d[2]), "+f"(d[3])
                 : "r"(a[0]), "r"(a[1]), "r"(a[2]), "r"(a[3]), "r"(b[0]), "r"(b[1]));
}
__device__ __forceinline__ uint32_t swz(uint32_t off) { return off ^ ((off >> 3) & 0x70); }

// ======================= prep kernels =======================
__global__ void zero_both() {
    int i = blockIdx.x * blockDim.x + threadIdx.x;
    if (i < N_NODES) { g_dinv[i] = 0.f; g_degi[i] = 0; }
}
__global__ void deg_kernel(const int* __restrict__ ei, const float* __restrict__ ea) {
    int e = blockIdx.x * blockDim.x + threadIdx.x;
    if (e < N_EDGES) {
        int dst = ei[N_EDGES + e];
        atomicAdd(&g_dinv[dst], ea[e]);
        atomicAdd(&g_degi[dst], 1);
    }
}
__global__ void scan_kernel() {
    __shared__ int sh[1024];
    const int CH = (N_NODES + 1023) / 1024;
    int tid = threadIdx.x;
    int base = tid * CH;
    int s = 0;
    for (int j = 0; j < CH; j++) {
        int i = base + j;
        if (i < N_NODES) {
            g_dinv[i] = rsqrtf(g_dinv[i] + 1.0f);
            s += g_degi[i];
        }
    }
    sh[tid] = s;
    __syncthreads();
    for (int off = 1; off < 1024; off <<= 1) {
        int v = (tid >= off) ? sh[tid - off] : 0;
        __syncthreads();
        sh[tid] += v;
        __syncthreads();
    }
    int run = tid ? sh[tid - 1] : 0;
    for (int j = 0; j < CH; j++) {
        int i = base + j;
        if (i < N_NODES) {
            g_rp[i] = run;
            g_cursor[i] = run;
            run += g_degi[i];
        }
    }
    if (tid == 1023) g_rp[N_NODES] = sh[1023];
}
__global__ void scatter_kernel(const int* __restrict__ ei, const float* __restrict__ ea) {
    int e = blockIdx.x * blockDim.x + threadIdx.x;
    if (e >= N_EDGES) return;
    int src = ei[e];
    int dst = ei[N_EDGES + e];
    float w = g_dinv[src] * ea[e] * g_dinv[dst];
    int pos = atomicAdd(&g_cursor[dst], 1);
    g_edge[pos] = make_int2(src, __float_as_int(w));
}

__global__ void pre_all(const float* __restrict__ layer_table, const float* __restrict__ rel_table,
                        const float* __restrict__ color_table, const float* __restrict__ W1) {
    __shared__ float s[256];
    int b = blockIdx.x, j = threadIdx.x;
    const float* tab;
    float* outp;
    int Kt, off;
    if (b < 3)       { tab = layer_table + (size_t)b * 250;        outp = g_preL + (size_t)b * F1;        Kt = 250; off = 0; }
    else if (b < 14) { tab = rel_table + (size_t)(b - 3) * 250;    outp = g_preR + (size_t)(b - 3) * F1;  Kt = 250; off = 1250; }
    else {
        int q = b - 14;
        int p = q >> 8, c = q & 255;
        tab = color_table + (size_t)c * 85;
        outp = g_preC + (size_t)q * F1;
        Kt = 85; off = 1500 + 85 * p;
    }
    if (j < Kt) s[j] = tab[j];
    __syncthreads();
    float acc = 0.f;
    for (int k = 0; k < Kt; k++) acc = fmaf(s[k], W1[(size_t)(off + k) * F1 + j], acc);
    outp[j] = acc;
}

__global__ void split_base(const float* __restrict__ x) {
    int i = blockIdx.x;
    const float* xr = x + (size_t)i * XCOLS;
    __half* a = g_A2 + (size_t)i * KP1;
    for (int k = threadIdx.x; k < KP1; k += blockDim.x) {
        float v = (k < FS) ? xr[1 + k] : 0.f;
        a[k] = __float2half(v);
    }
    int j = threadIdx.x;
    if (j < 128) {
        int li = (int)xr[0] - 1;
        int ri = __float2int_rn(fabsf(xr[FS + 1]) * 10.0f);
        int c0 = (int)xr[XCOLS - 3];
        int c1 = (int)xr[XCOLS - 2];
        int c2 = (int)xr[XCOLS - 1];
        float4 pa = ((const float4*)(g_preL + (size_t)li * F1))[j];
        float4 pb = ((const float4*)(g_preR + (size_t)ri * F1))[j];
        float4 u = ((const float4*)(g_preC + ((size_t)(0 * 256 + c0)) * F1))[j];
        float4 v = ((const float4*)(g_preC + ((size_t)(1 * 256 + c1)) * F1))[j];
        float4 w = ((const float4*)(g_preC + ((size_t)(2 * 256 + c2)) * F1))[j];
        __half2 o0 = __floats2half2_rn(pa.x + pb.x + u.x + v.x + w.x, pa.y + pb.y + u.y + v.y + w.y);
        __half2 o1 = __floats2half2_rn(pa.z + pb.z + u.z + v.z + w.z, pa.w + pb.w + u.w + v.w + w.w);
        uint2 pk;
        pk.x = *(uint32_t*)&o0;
        pk.y = *(uint32_t*)&o1;
        ((uint2*)(g_base + (size_t)i * F1))[j] = pk;
    }
}

#define W1N (F1 * KP1)
#define W2N (F2 * F1)
#define W3N (F3 * F2)
__global__ void convW(const float* __restrict__ W1, const float* __restrict__ W2,
                      const float* __restrict__ W3) {
    int idx = blockIdx.x * blockDim.x + threadIdx.x;
    if (idx < W1N) {
        int n = idx / KP1, k = idx % KP1;
        float v = (k < FS) ? W1[(size_t)(250 + k) * F1 + n] : 0.f;
        g_W1T[idx] = __float2half(v);
    } else if (idx < W1N + W2N) {
        int q = idx - W1N;
        int n = q / F1, k = q % F1;
        g_W2T[q] = __float2half(W2[(size_t)k * F2 + n]);
    } else if (idx < W1N + W2N + W3N) {
        int q = idx - W1N - W2N;
        int n = q / F2, k = q % F2;
        g_W3T[q] = __float2half(W3[(size_t)k * F3 + n]);
    }
}

// ======================= mma.sync fp16 GEMM (3-stage, 2 CTAs/SM, bn0 offset) =======================
template<int BN>
__device__ __forceinline__ void load_stage(const __half* __restrict__ A,
                                           const __half* __restrict__ B,
                                           int bm, int bn, int Kp, int k0, int M,
                                           uint32_t sA, uint32_t sB) {
    int t = threadIdx.x;
#pragma unroll
    for (int i = 0; i < 4; i++) {
        int idx = t + i * 256;
        int row = idx >> 3, seg = idx & 7;
        int gr = bm + row;
        bool p = gr < M;
        const void* src = A + (size_t)(p ? gr : 0) * Kp + k0 + seg * 8;
        cp16(sA + swz(row * 128 + seg * 16), src, p);
    }
#pragma unroll
    for (int i = 0; i < BN * 8 / 256; i++) {
        int idx = t + i * 256;
        int row = idx >> 3, seg = idx & 7;
        const void* src = B + (size_t)(bn + row) * Kp + k0 + seg * 8;
        cp16(sB + swz(row * 128 + seg * 16), src, true);
    }
}

template<int BN, bool ADD_BASE, bool HALF_OUT>
__global__ __launch_bounds__(256, 2) void mma_gemm(const __half* __restrict__ A,
                                                   const __half* __restrict__ B,
                                                   const __half* __restrict__ base,
                                                   void* __restrict__ Cv,
                                                   int M, int Kp, int Nn, int bn0) {
    extern __shared__ char smem[];
    constexpr int WN = BN / 2;
    constexpr int SS = (128 + BN) * 128;
    uint32_t sb = smem_u32(smem);
    int tid = threadIdx.x, wid = tid >> 5, lane = tid & 31;
    int bm = blockIdx.y * 128, bn = bn0 + blockIdx.x * BN;
    int wm = (wid & 3) * 32;
    int wn = (wid >> 2) * WN;

    float acc[2][WN / 8][4];
#pragma unroll
    for (int i = 0; i < 2; i++)
#pragma unroll
        for (int j = 0; j < WN / 8; j++)
#pragma unroll
            for (int q = 0; q < 4; q++) acc[i][j][q] = 0.f;

    int nT = Kp >> 6;
#pragma unroll
    for (int s = 0; s < 2; s++) {
        uint32_t sp = sb + (uint32_t)s * SS;
        load_stage<BN>(A, B, bm, bn, Kp, s * 64, M, sp, sp + 128 * 128);
        CP_COMMIT();
    }

    for (int t = 0; t < nT; t++) {
        if (t + 2 < nT) {
            uint32_t sp = sb + (uint32_t)((t + 2) % 3) * SS;
            load_stage<BN>(A, B, bm, bn, Kp, (t + 2) * 64, M, sp, sp + 128 * 128);
        }
        CP_COMMIT();
        CP_WAIT2();
        __syncthreads();

        uint32_t sA = sb + (uint32_t)(t % 3) * SS;
        uint32_t sB = sA + 128 * 128;
#pragma unroll
        for (int ks = 0; ks < 4; ks++) {
            uint32_t af[2][4];
#pragma unroll
            for (int mi = 0; mi < 2; mi++) {
                int row = wm + mi * 16 + (lane & 15);
                ldsm_x4(af[mi], sA + swz(row * 128 + ks * 32 + ((lane >> 4) << 4)));
            }
#pragma unroll
            for (int nj = 0; nj < WN / 16; nj++) {
                uint32_t bf[4];
                int row = wn + nj * 16 + (lane & 7) + ((lane >> 4) << 3);
                ldsm_x4(bf, sB + swz(row * 128 + ks * 32 + (((lane >> 3) & 1) << 4)));
                mma_f16(acc[0][2 * nj],     af[0], bf);
                mma_f16(acc[0][2 * nj + 1], af[0], bf + 2);
                mma_f16(acc[1][2 * nj],     af[1], bf);
                mma_f16(acc[1][2 * nj + 1], af[1], bf + 2);
            }
        }
        __syncthreads();
    }

#pragma unroll
    for (int mi = 0; mi < 2; mi++) {
#pragma unroll
        for (int nj = 0; nj < WN / 8; nj++) {
            int row = bm + wm + mi * 16 + (lane >> 2);
            int col = bn + wn + nj * 8 + (lane & 3) * 2;
#pragma unroll
            for (int h = 0; h < 2; h++) {
                int r = row + h * 8;
                if (r < M) {
                    float2 v = make_float2(acc[mi][nj][h * 2], acc[mi][nj][h * 2 + 1]);
                    if (ADD_BASE) {
                        __half2 b2 = *(const __half2*)(base + (size_t)r * Nn + col);
                        float2 bf2 = __half22float2(b2);
                        v.x += bf2.x; v.y += bf2.y;
                    }
                    if (HALF_OUT) {
                        *(__half2*)((__half*)Cv + (size_t)r * Nn + col) = __floats2half2_rn(v.x, v.y);
                    } else {
                        *(float2*)((float*)Cv + (size_t)r * Nn + col) = v;
                    }
                }
            }
        }
    }
}

// ======================= fused CSR aggregation (column block, fp16 gather) =======================
template<int F, int COLS, int NPB>
__global__ __launch_bounds__(128) void csr_agg_h(const __half* __restrict__ t,
                                                 const float* __restrict__ b,
                                                 __half* __restrict__ hs, int col0) {
    constexpr int C = COLS / 8;
    constexpr int RS = F / 8;
    int node = blockIdx.x * NPB + threadIdx.x / C;
    int ch = threadIdx.x % C;
    if (node >= N_NODES) return;
    int c8 = (col0 >> 3) + ch;
    int beg = g_rp[node], end = g_rp[node + 1];
    const uint4* tv = (const uint4*)t;
    float d = g_dinv[node];
    float dd = d * d;
    float acc[8];
    {
        uint4 sv = tv[(size_t)node * RS + c8];
        const __half2* h2 = (const __half2*)&sv;
        float4 b0 = ((const float4*)b)[c8 * 2];
        float4 b1v = ((const float4*)b)[c8 * 2 + 1];
        float bb[8] = {b0.x, b0.y, b0.z, b0.w, b1v.x, b1v.y, b1v.z, b1v.w};
#pragma unroll
        for (int q = 0; q < 4; q++) {
            float2 f2 = __half22float2(h2[q]);
            acc[q * 2 + 0] = fmaf(f2.x, dd, bb[q * 2 + 0]);
            acc[q * 2 + 1] = fmaf(f2.y, dd, bb[q * 2 + 1]);
        }
    }
    int stop = beg + ((end - beg) & ~3);
    int i = beg;
    int2 e0, e1, e2, e3;
    if (i < stop) {
        e0 = g_edge[i]; e1 = g_edge[i + 1]; e2 = g_edge[i + 2]; e3 = g_edge[i + 3];
    }
    while (i < stop) {
        int j = i + 4;
        int2 f0, f1, f2n, f3;
        if (j < stop) {
            f0 = g_edge[j]; f1 = g_edge[j + 1]; f2n = g_edge[j + 2]; f3 = g_edge[j + 3];
        }
        uint4 v0 = tv[(size_t)e0.x * RS + c8];
        uint4 v1 = tv[(size_t)e1.x * RS + c8];
        uint4 v2 = tv[(size_t)e2.x * RS + c8];
        uint4 v3 = tv[(size_t)e3.x * RS + c8];
        float w0 = __int_as_float(e0.y), w1 = __int_as_float(e1.y);
        float w2 = __int_as_float(e2.y), w3 = __int_as_float(e3.y);
        const __half2* a0 = (const __half2*)&v0;
        const __half2* a1 = (const __half2*)&v1;
        const __half2* a2 = (const __half2*)&v2;
        const __half2* a3 = (const __half2*)&v3;
#pragma unroll
        for (int q = 0; q < 4; q++) {
            float2 g0 = __half22float2(a0[q]);
            float2 g1 = __half22float2(a1[q]);
            float2 g2 = __half22float2(a2[q]);
            float2 g3 = __half22float2(a3[q]);
            acc[q * 2 + 0] += g0.x * w0 + g1.x * w1 + g2.x * w2 + g3.x * w3;
            acc[q * 2 + 1] += g0.y * w0 + g1.y * w1 + g2.y * w2 + g3.y * w3;
        }
        e0 = f0; e1 = f1; e2 = f2n; e3 = f3;
        i = j;
    }
    for (; i < end; i++) {
        int2 eo = g_edge[i];
        float w0 = __int_as_float(eo.y);
        uint4 v0 = tv[(size_t)eo.x * RS + c8];
        const __half2* a0 = (const __half2*)&v0;
#pragma unroll
        for (int q = 0; q < 4; q++) {
            float2 g0 = __half22float2(a0[q]);
            acc[q * 2 + 0] += g0.x * w0;
            acc[q * 2 + 1] += g0.y * w0;
        }
    }
    __half h[8];
#pragma unroll
    for (int q = 0; q < 8; q++) {
        float u = acc[q] > 0.f ? acc[q] : 0.01f * acc[q];
        h[q] = __float2half(u);
    }
    *(uint4*)(hs + (size_t)node * F + c8 * 8) = *(uint4*)h;
}

template<int F, int NPB>
__global__ __launch_bounds__(128) void csr_agg_proj(const float* __restrict__ t,
                                                    const float* __restrict__ b,
                                                    const float* __restrict__ Wp,
                                                    const float* __restrict__ bp,
                                                    float* __restrict__ out) {
    constexpr int C = F / 4;
    int node = blockIdx.x * NPB + threadIdx.x / C;
    int ch = threadIdx.x % C;
    if (node >= N_NODES) return;
    int beg = g_rp[node], end = g_rp[node + 1];
    const float4* tv = (const float4*)t;
    float d = g_dinv[node];
    float dd = d * d;
    float4 self = tv[(size_t)node * C + ch];
    float4 bv = ((const float4*)b)[ch];
    float4 acc = make_float4(fmaf(self.x, dd, bv.x), fmaf(self.y, dd, bv.y),
                             fmaf(self.z, dd, bv.z), fmaf(self.w, dd, bv.w));
    int stop = beg + ((end - beg) & ~3);
    int i = beg;
    int2 e0, e1, e2, e3;
    if (i < stop) {
        e0 = g_edge[i]; e1 = g_edge[i + 1]; e2 = g_edge[i + 2]; e3 = g_edge[i + 3];
    }
    while (i < stop) {
        int j = i + 4;
        int2 f0, f1, f2n, f3;
        if (j < stop) {
            f0 = g_edge[j]; f1 = g_edge[j + 1]; f2n = g_edge[j + 2]; f3 = g_edge[j + 3];
        }
        float4 v0 = tv[(size_t)e0.x * C + ch];
        float4 v1 = tv[(size_t)e1.x * C + ch];
        float4 v2 = tv[(size_t)e2.x * C + ch];
        float4 v3 = tv[(size_t)e3.x * C + ch];
        float w0 = __int_as_float(e0.y), w1 = __int_as_float(e1.y);
        float w2 = __int_as_float(e2.y), w3 = __int_as_float(e3.y);
        acc.x += v0.x * w0 + v1.x * w1 + v2.x * w2 + v3.x * w3;
        acc.y += v0.y * w0 + v1.y * w1 + v2.y * w2 + v3.y * w3;
        acc.z += v0.z * w0 + v1.z * w1 + v2.z * w2 + v3.z * w3;
        acc.w += v0.w * w0 + v1.w * w1 + v2.w * w2 + v3.w * w3;
        e0 = f0; e1 = f1; e2 = f2n; e3 = f3;
        i = j;
    }
    for (; i < end; i++) {
        int2 eo = g_edge[i];
        float w0 = __int_as_float(eo.y);
        float4 v0 = tv[(size_t)eo.x * C + ch];
        acc.x += v0.x * w0; acc.y += v0.y * w0; acc.z += v0.z * w0; acc.w += v0.w * w0;
    }
    float f[4] = {acc.x, acc.y, acc.z, acc.w};
#pragma unroll
    for (int q = 0; q < 4; q++) f[q] = f[q] > 0.f ? f[q] : 0.01f * f[q];
    float a0 = 0.f, a1 = 0.f, a2 = 0.f;
#pragma unroll
    for (int q = 0; q < 4; q++) {
        int k = ch * 4 + q;
        a0 = fmaf(f[q], __ldg(Wp + k * 3 + 0), a0);
        a1 = fmaf(f[q], __ldg(Wp + k * 3 + 1), a1);
        a2 = fmaf(f[q], __ldg(Wp + k * 3 + 2), a2);
    }
#pragma unroll
    for (int off = C / 2; off; off >>= 1) {
        a0 += __shfl_down_sync(0xffffffffu, a0, off, C);
        a1 += __shfl_down_sync(0xffffffffu, a1, off, C);
        a2 += __shfl_down_sync(0xffffffffu, a2, off, C);
    }
    if (ch == 0) {
        out[(size_t)node * 3 + 0] = a0 + bp[0];
        out[(size_t)node * 3 + 1] = a1 + bp[1];
        out[(size_t)node * 3 + 2] = a2 + bp[2];
    }
}

// ======================= launch =======================
extern "C" void kernel_launch(void* const* d_in, const int* in_sizes, int n_in,
                              void* d_out, int out_size) {
    const float* x           = (const float*)d_in[0];
    const int*   edge_index  = (const int*)  d_in[1];
    const float* edge_attr   = (const float*)d_in[2];
    const float* layer_table = (const float*)d_in[3];
    const float* rel_table   = (const float*)d_in[4];
    const float* color_table = (const float*)d_in[5];
    const float* W1 = (const float*)d_in[6];
    const float* b1 = (const float*)d_in[7];
    const float* W2 = (const float*)d_in[8];
    const float* b2 = (const float*)d_in[9];
    const float* W3 = (const float*)d_in[10];
    const float* b3 = (const float*)d_in[11];
    const float* Wp = (const float*)d_in[12];
    const float* bp = (const float*)d_in[13];
    float* out = (float*)d_out;

    __half *p_A2, *p_h2s, *p_h3s, *p_W1T, *p_W2T, *p_W3T, *p_base;
    float *p_t;
    cudaGetSymbolAddress((void**)&p_A2,   g_A2);
    cudaGetSymbolAddress((void**)&p_h2s,  g_h2s);
    cudaGetSymbolAddress((void**)&p_h3s,  g_h3s);
    cudaGetSymbolAddress((void**)&p_W1T,  g_W1T);
    cudaGetSymbolAddress((void**)&p_W2T,  g_W2T);
    cudaGetSymbolAddress((void**)&p_W3T,  g_W3T);
    cudaGetSymbolAddress((void**)&p_base, g_base);
    cudaGetSymbolAddress((void**)&p_t,    g_t);
    __half* p_th = (__half*)p_t;

    const int T = 256;
    const int SM128 = 3 * (128 + 128) * 128;   // 98304
    const int SM64  = 3 * (128 + 64) * 128;    // 73728
    cudaFuncSetAttribute((const void*)mma_gemm<128, true,  true>,  cudaFuncAttributeMaxDynamicSharedMemorySize, SM128);
    cudaFuncSetAttribute((const void*)mma_gemm<128, false, true>,  cudaFuncAttributeMaxDynamicSharedMemorySize, SM128);
    cudaFuncSetAttribute((const void*)mma_gemm<64,  false, false>, cudaFuncAttributeMaxDynamicSharedMemorySize, SM64);

    // Side stream + events: parallel graph branches under capture.
    cudaStream_t s2;
    cudaStreamCreateWithFlags(&s2, cudaStreamNonBlocking);
    cudaEvent_t evFork, evG1a, evG1b, evA1b, evG2a, evA2a;
    cudaEventCreateWithFlags(&evFork, cudaEventDisableTiming);
    cudaEventCreateWithFlags(&evG1a,  cudaEventDisableTiming);
    cudaEventCreateWithFlags(&evG1b,  cudaEventDisableTiming);
    cudaEventCreateWithFlags(&evA1b,  cudaEventDisableTiming);
    cudaEventCreateWithFlags(&evG2a,  cudaEventDisableTiming);
    cudaEventCreateWithFlags(&evA2a,  cudaEventDisableTiming);

    cudaEventRecord(evFork, 0);
    cudaStreamWaitEvent(s2, evFork, 0);

    // ---- side branch: CSR build ----
    zero_both<<<(N_NODES + T - 1) / T, T, 0, s2>>>();
    deg_kernel<<<(N_EDGES + T - 1) / T, T, 0, s2>>>(edge_index, edge_attr);
    scan_kernel<<<1, 1024, 0, s2>>>();
    scatter_kernel<<<(N_EDGES + T - 1) / T, T, 0, s2>>>(edge_index, edge_attr);

    // ---- main branch: GEMM inputs ----
    convW<<<(W1N + W2N + W3N + T - 1) / T, T>>>(W1, W2, W3);
    pre_all<<<782, 512>>>(layer_table, rel_table, color_table, W1);
    split_base<<<N_NODES, T>>>(x);

    const int MT = (N_NODES + 127) / 128;   // 157

    // ======== layer 1: 3-way split-N pipeline (256 / 128 / 128 cols) ========
    mma_gemm<128, true, true><<<dim3(2, MT), T, SM128>>>(p_A2, p_W1T, p_base, p_th, N_NODES, KP1, F1, 0);
    cudaEventRecord(evG1a, 0);
    mma_gemm<128, true, true><<<dim3(1, MT), T, SM128>>>(p_A2, p_W1T, p_base, p_th, N_NODES, KP1, F1, 256);
    cudaEventRecord(evG1b, 0);
    mma_gemm<128, true, true><<<dim3(1, MT), T, SM128>>>(p_A2, p_W1T, p_base, p_th, N_NODES, KP1, F1, 384);

    // s2 (already ordered after CSR): agg cols 0-255 under G1b+G1c, then cols 256-383 under G1c
    cudaStreamWaitEvent(s2, evG1a, 0);
    csr_agg_h<F1, 256, 4><<<(N_NODES + 3) / 4, 128, 0, s2>>>(p_th, b1, p_h2s, 0);
    cudaStreamWaitEvent(s2, evG1b, 0);
    csr_agg_h<F1, 128, 8><<<(N_NODES + 7) / 8, 128, 0, s2>>>(p_th, b1, p_h2s, 256);
    cudaEventRecord(evA1b, s2);

    // main: exposed tail = cols 384-511 only
    cudaStreamWaitEvent(0, evA1b, 0);
    csr_agg_h<F1, 128, 8><<<(N_NODES + 7) / 8, 128>>>(p_th, b1, p_h2s, 384);

    // ======== layer 2: split-N pipeline (agg writes g_h3s — no aliasing with g_h2s input) ========
    mma_gemm<128, false, true><<<dim3(1, MT), T, SM128>>>(p_h2s, p_W2T, nullptr, p_th, N_NODES, F1, F2, 0);
    cudaEventRecord(evG2a, 0);
    mma_gemm<128, false, true><<<dim3(1, MT), T, SM128>>>(p_h2s, p_W2T, nullptr, p_th, N_NODES, F1, F2, 128);

    cudaStreamWaitEvent(s2, evG2a, 0);
    csr_agg_h<F2, 128, 8><<<(N_NODES + 7) / 8, 128, 0, s2>>>(p_th, b2, p_h3s, 0);
    cudaEventRecord(evA2a, s2);

    cudaStreamWaitEvent(0, evA2a, 0);
    csr_agg_h<F2, 128, 8><<<(N_NODES + 7) / 8, 128>>>(p_th, b2, p_h3s, 128);

    // ======== layer 3 (serial, projection fused; reads g_h3s) ========
    mma_gemm<64, false, false><<<dim3(1, MT), T, SM64>>>(p_h3s, p_W3T, nullptr, p_t, N_NODES, F2, F3, 0);
    csr_agg_proj<F3, 8><<<(N_NODES + 7) / 8, 128>>>(p_t, b3, Wp, bp, out);
}

// round 17
// speedup vs baseline: 1.1167x; 1.1167x over previous
#include <cuda_runtime.h>
#include <cuda_fp16.h>
#include <math.h>
#include <stdint.h>

#define N_NODES 20000
#define N_EDGES 320000
#define FS      1000
#define XCOLS   1005
#define F1      512
#define F2      256
#define F3      64
#define KP1     1024             // padded resnet K

// ======================= static scratch =======================
__device__ __half g_A2 [(size_t)N_NODES * KP1];
__device__ __half g_h2s[(size_t)N_NODES * F1];   // layer-1 activations (GEMM2 input)
__device__ __half g_h3s[(size_t)N_NODES * F2];   // layer-2 activations (GEMM3 input)
__device__ __half g_W1T[(size_t)F1 * KP1];
__device__ __half g_W2T[(size_t)F2 * F1];
__device__ __half g_W3T[(size_t)F3 * F2];
__device__ __half g_base[(size_t)N_NODES * F1];  // fp16 table contribution
__device__ float g_t   [(size_t)N_NODES * F1];
__device__ float g_dinv[N_NODES];
__device__ float g_preL[3 * F1];
__device__ float g_preR[11 * F1];
__device__ float g_preC[3 * 256 * F1];
__device__ int   g_degi[N_NODES];
__device__ int   g_rp[N_NODES + 1];
__device__ int   g_cursor[N_NODES];
__device__ int2  g_edge[N_EDGES];

// ======================= PTX helpers =======================
__device__ __forceinline__ uint32_t smem_u32(const void* p) {
    uint32_t a;
    asm("{ .reg .u64 t; cvta.to.shared.u64 t, %1; cvt.u32.u64 %0, t; }" : "=r"(a) : "l"(p));
    return a;
}
__device__ __forceinline__ void cp16(uint32_t dst, const void* src, bool pred) {
    int sz = pred ? 16 : 0;
    asm volatile("cp.async.cg.shared.global [%0], [%1], 16, %2;"
                 :: "r"(dst), "l"(src), "r"(sz) : "memory");
}
#define CP_COMMIT() asm volatile("cp.async.commit_group;" ::: "memory")
#define CP_WAIT2()  asm volatile("cp.async.wait_group 2;" ::: "memory")

__device__ __forceinline__ void ldsm_x4(uint32_t* r, uint32_t addr) {
    asm volatile("ldmatrix.sync.aligned.m8n8.x4.shared.b16 {%0,%1,%2,%3}, [%4];"
                 : "=r"(r[0]), "=r"(r[1]), "=r"(r[2]), "=r"(r[3]) : "r"(addr));
}
__device__ __forceinline__ void mma_f16(float* d, const uint32_t* a, const uint32_t* b) {
    asm volatile("mma.sync.aligned.m16n8k16.row.col.f32.f16.f16.f32 "
                 "{%0,%1,%2,%3}, {%4,%5,%6,%7}, {%8,%9}, {%0,%1,%2,%3};"
                 : "+f"(d[0]), "+f"(d[1]), "+f"(d[2]), "+f"(d[3])
                 : "r"(a[0]), "r"(a[1]), "r"(a[2]), "r"(a[3]), "r"(b[0]), "r"(b[1]));
}
__device__ __forceinline__ uint32_t swz(uint32_t off) { return off ^ ((off >> 3) & 0x70); }

// ======================= prep kernels =======================
__global__ void zero_both() {
    int i = blockIdx.x * blockDim.x + threadIdx.x;
    if (i < N_NODES) { g_dinv[i] = 0.f; g_degi[i] = 0; }
}
__global__ void deg_kernel(const int* __restrict__ ei, const float* __restrict__ ea) {
    int e = blockIdx.x * blockDim.x + threadIdx.x;
    if (e < N_EDGES) {
        int dst = ei[N_EDGES + e];
        atomicAdd(&g_dinv[dst], ea[e]);
        atomicAdd(&g_degi[dst], 1);
    }
}
__global__ void scan_kernel() {
    __shared__ int sh[1024];
    const int CH = (N_NODES + 1023) / 1024;
    int tid = threadIdx.x;
    int base = tid * CH;
    int s = 0;
    for (int j = 0; j < CH; j++) {
        int i = base + j;
        if (i < N_NODES) {
            g_dinv[i] = rsqrtf(g_dinv[i] + 1.0f);
            s += g_degi[i];
        }
    }
    sh[tid] = s;
    __syncthreads();
    for (int off = 1; off < 1024; off <<= 1) {
        int v = (tid >= off) ? sh[tid - off] : 0;
        __syncthreads();
        sh[tid] += v;
        __syncthreads();
    }
    int run = tid ? sh[tid - 1] : 0;
    for (int j = 0; j < CH; j++) {
        int i = base + j;
        if (i < N_NODES) {
            g_rp[i] = run;
            g_cursor[i] = run;
            run += g_degi[i];
        }
    }
    if (tid == 1023) g_rp[N_NODES] = sh[1023];
}
__global__ void scatter_kernel(const int* __restrict__ ei, const float* __restrict__ ea) {
    int e = blockIdx.x * blockDim.x + threadIdx.x;
    if (e >= N_EDGES) return;
    int src = ei[e];
    int dst = ei[N_EDGES + e];
    float w = g_dinv[src] * ea[e] * g_dinv[dst];
    int pos = atomicAdd(&g_cursor[dst], 1);
    g_edge[pos] = make_int2(src, __float_as_int(w));
}

__global__ void pre_all(const float* __restrict__ layer_table, const float* __restrict__ rel_table,
                        const float* __restrict__ color_table, const float* __restrict__ W1) {
    __shared__ float s[256];
    int b = blockIdx.x, j = threadIdx.x;
    const float* tab;
    float* outp;
    int Kt, off;
    if (b < 3)       { tab = layer_table + (size_t)b * 250;        outp = g_preL + (size_t)b * F1;        Kt = 250; off = 0; }
    else if (b < 14) { tab = rel_table + (size_t)(b - 3) * 250;    outp = g_preR + (size_t)(b - 3) * F1;  Kt = 250; off = 1250; }
    else {
        int q = b - 14;
        int p = q >> 8, c = q & 255;
        tab = color_table + (size_t)c * 85;
        outp = g_preC + (size_t)q * F1;
        Kt = 85; off = 1500 + 85 * p;
    }
    if (j < Kt) s[j] = tab[j];
    __syncthreads();
    float acc = 0.f;
    for (int k = 0; k < Kt; k++) acc = fmaf(s[k], W1[(size_t)(off + k) * F1 + j], acc);
    outp[j] = acc;
}

__global__ void split_base(const float* __restrict__ x) {
    int i = blockIdx.x;
    const float* xr = x + (size_t)i * XCOLS;
    __half* a = g_A2 + (size_t)i * KP1;
    for (int k = threadIdx.x; k < KP1; k += blockDim.x) {
        float v = (k < FS) ? xr[1 + k] : 0.f;
        a[k] = __float2half(v);
    }
    int j = threadIdx.x;
    if (j < 128) {
        int li = (int)xr[0] - 1;
        int ri = __float2int_rn(fabsf(xr[FS + 1]) * 10.0f);
        int c0 = (int)xr[XCOLS - 3];
        int c1 = (int)xr[XCOLS - 2];
        int c2 = (int)xr[XCOLS - 1];
        float4 pa = ((const float4*)(g_preL + (size_t)li * F1))[j];
        float4 pb = ((const float4*)(g_preR + (size_t)ri * F1))[j];
        float4 u = ((const float4*)(g_preC + ((size_t)(0 * 256 + c0)) * F1))[j];
        float4 v = ((const float4*)(g_preC + ((size_t)(1 * 256 + c1)) * F1))[j];
        float4 w = ((const float4*)(g_preC + ((size_t)(2 * 256 + c2)) * F1))[j];
        __half2 o0 = __floats2half2_rn(pa.x + pb.x + u.x + v.x + w.x, pa.y + pb.y + u.y + v.y + w.y);
        __half2 o1 = __floats2half2_rn(pa.z + pb.z + u.z + v.z + w.z, pa.w + pb.w + u.w + v.w + w.w);
        uint2 pk;
        pk.x = *(uint32_t*)&o0;
        pk.y = *(uint32_t*)&o1;
        ((uint2*)(g_base + (size_t)i * F1))[j] = pk;
    }
}

#define W1N (F1 * KP1)
#define W2N (F2 * F1)
#define W3N (F3 * F2)
__global__ void convW(const float* __restrict__ W1, const float* __restrict__ W2,
                      const float* __restrict__ W3) {
    int idx = blockIdx.x * blockDim.x + threadIdx.x;
    if (idx < W1N) {
        int n = idx / KP1, k = idx % KP1;
        float v = (k < FS) ? W1[(size_t)(250 + k) * F1 + n] : 0.f;
        g_W1T[idx] = __float2half(v);
    } else if (idx < W1N + W2N) {
        int q = idx - W1N;
        int n = q / F1, k = q % F1;
        g_W2T[q] = __float2half(W2[(size_t)k * F2 + n]);
    } else if (idx < W1N + W2N + W3N) {
        int q = idx - W1N - W2N;
        int n = q / F2, k = q % F2;
        g_W3T[q] = __float2half(W3[(size_t)k * F3 + n]);
    }
}

// ======================= mma.sync fp16 GEMM (3-stage, 2 CTAs/SM, bn0 offset) =======================
template<int BN>
__device__ __forceinline__ void load_stage(const __half* __restrict__ A,
                                           const __half* __restrict__ B,
                                           int bm, int bn, int Kp, int k0, int M,
                                           uint32_t sA, uint32_t sB) {
    int t = threadIdx.x;
#pragma unroll
    for (int i = 0; i < 4; i++) {
        int idx = t + i * 256;
        int row = idx >> 3, seg = idx & 7;
        int gr = bm + row;
        bool p = gr < M;
        const void* src = A + (size_t)(p ? gr : 0) * Kp + k0 + seg * 8;
        cp16(sA + swz(row * 128 + seg * 16), src, p);
    }
#pragma unroll
    for (int i = 0; i < BN * 8 / 256; i++) {
        int idx = t + i * 256;
        int row = idx >> 3, seg = idx & 7;
        const void* src = B + (size_t)(bn + row) * Kp + k0 + seg * 8;
        cp16(sB + swz(row * 128 + seg * 16), src, true);
    }
}

template<int BN, bool ADD_BASE, bool HALF_OUT>
__global__ __launch_bounds__(256, 2) void mma_gemm(const __half* __restrict__ A,
                                                   const __half* __restrict__ B,
                                                   const __half* __restrict__ base,
                                                   void* __restrict__ Cv,
                                                   int M, int Kp, int Nn, int bn0) {
    extern __shared__ char smem[];
    constexpr int WN = BN / 2;
    constexpr int SS = (128 + BN) * 128;
    uint32_t sb = smem_u32(smem);
    int tid = threadIdx.x, wid = tid >> 5, lane = tid & 31;
    int bm = blockIdx.y * 128, bn = bn0 + blockIdx.x * BN;
    int wm = (wid & 3) * 32;
    int wn = (wid >> 2) * WN;

    float acc[2][WN / 8][4];
#pragma unroll
    for (int i = 0; i < 2; i++)
#pragma unroll
        for (int j = 0; j < WN / 8; j++)
#pragma unroll
            for (int q = 0; q < 4; q++) acc[i][j][q] = 0.f;

    int nT = Kp >> 6;
#pragma unroll
    for (int s = 0; s < 2; s++) {
        uint32_t sp = sb + (uint32_t)s * SS;
        load_stage<BN>(A, B, bm, bn, Kp, s * 64, M, sp, sp + 128 * 128);
        CP_COMMIT();
    }

    for (int t = 0; t < nT; t++) {
        if (t + 2 < nT) {
            uint32_t sp = sb + (uint32_t)((t + 2) % 3) * SS;
            load_stage<BN>(A, B, bm, bn, Kp, (t + 2) * 64, M, sp, sp + 128 * 128);
        }
        CP_COMMIT();
        CP_WAIT2();
        __syncthreads();

        uint32_t sA = sb + (uint32_t)(t % 3) * SS;
        uint32_t sB = sA + 128 * 128;
#pragma unroll
        for (int ks = 0; ks < 4; ks++) {
            uint32_t af[2][4];
#pragma unroll
            for (int mi = 0; mi < 2; mi++) {
                int row = wm + mi * 16 + (lane & 15);
                ldsm_x4(af[mi], sA + swz(row * 128 + ks * 32 + ((lane >> 4) << 4)));
            }
#pragma unroll
            for (int nj = 0; nj < WN / 16; nj++) {
                uint32_t bf[4];
                int row = wn + nj * 16 + (lane & 7) + ((lane >> 4) << 3);
                ldsm_x4(bf, sB + swz(row * 128 + ks * 32 + (((lane >> 3) & 1) << 4)));
                mma_f16(acc[0][2 * nj],     af[0], bf);
                mma_f16(acc[0][2 * nj + 1], af[0], bf + 2);
                mma_f16(acc[1][2 * nj],     af[1], bf);
                mma_f16(acc[1][2 * nj + 1], af[1], bf + 2);
            }
        }
        __syncthreads();
    }

#pragma unroll
    for (int mi = 0; mi < 2; mi++) {
#pragma unroll
        for (int nj = 0; nj < WN / 8; nj++) {
            int row = bm + wm + mi * 16 + (lane >> 2);
            int col = bn + wn + nj * 8 + (lane & 3) * 2;
#pragma unroll
            for (int h = 0; h < 2; h++) {
                int r = row + h * 8;
                if (r < M) {
                    float2 v = make_float2(acc[mi][nj][h * 2], acc[mi][nj][h * 2 + 1]);
                    if (ADD_BASE) {
                        __half2 b2 = *(const __half2*)(base + (size_t)r * Nn + col);
                        float2 bf2 = __half22float2(b2);
                        v.x += bf2.x; v.y += bf2.y;
                    }
                    if (HALF_OUT) {
                        *(__half2*)((__half*)Cv + (size_t)r * Nn + col) = __floats2half2_rn(v.x, v.y);
                    } else {
                        *(float2*)((float*)Cv + (size_t)r * Nn + col) = v;
                    }
                }
            }
        }
    }
}

// ======================= fused CSR aggregation (column block, fp16 gather) =======================
template<int F, int COLS, int NPB>
__global__ __launch_bounds__(128) void csr_agg_h(const __half* __restrict__ t,
                                                 const float* __restrict__ b,
                                                 __half* __restrict__ hs, int col0) {
    constexpr int C = COLS / 8;
    constexpr int RS = F / 8;
    int node = blockIdx.x * NPB + threadIdx.x / C;
    int ch = threadIdx.x % C;
    if (node >= N_NODES) return;
    int c8 = (col0 >> 3) + ch;
    int beg = g_rp[node], end = g_rp[node + 1];
    const uint4* tv = (const uint4*)t;
    float d = g_dinv[node];
    float dd = d * d;
    float acc[8];
    {
        uint4 sv = tv[(size_t)node * RS + c8];
        const __half2* h2 = (const __half2*)&sv;
        float4 b0 = ((const float4*)b)[c8 * 2];
        float4 b1v = ((const float4*)b)[c8 * 2 + 1];
        float bb[8] = {b0.x, b0.y, b0.z, b0.w, b1v.x, b1v.y, b1v.z, b1v.w};
#pragma unroll
        for (int q = 0; q < 4; q++) {
            float2 f2 = __half22float2(h2[q]);
            acc[q * 2 + 0] = fmaf(f2.x, dd, bb[q * 2 + 0]);
            acc[q * 2 + 1] = fmaf(f2.y, dd, bb[q * 2 + 1]);
        }
    }
    int stop = beg + ((end - beg) & ~3);
    int i = beg;
    int2 e0, e1, e2, e3;
    if (i < stop) {
        e0 = g_edge[i]; e1 = g_edge[i + 1]; e2 = g_edge[i + 2]; e3 = g_edge[i + 3];
    }
    while (i < stop) {
        int j = i + 4;
        int2 f0, f1, f2n, f3;
        if (j < stop) {
            f0 = g_edge[j]; f1 = g_edge[j + 1]; f2n = g_edge[j + 2]; f3 = g_edge[j + 3];
        }
        uint4 v0 = tv[(size_t)e0.x * RS + c8];
        uint4 v1 = tv[(size_t)e1.x * RS + c8];
        uint4 v2 = tv[(size_t)e2.x * RS + c8];
        uint4 v3 = tv[(size_t)e3.x * RS + c8];
        float w0 = __int_as_float(e0.y), w1 = __int_as_float(e1.y);
        float w2 = __int_as_float(e2.y), w3 = __int_as_float(e3.y);
        const __half2* a0 = (const __half2*)&v0;
        const __half2* a1 = (const __half2*)&v1;
        const __half2* a2 = (const __half2*)&v2;
        const __half2* a3 = (const __half2*)&v3;
#pragma unroll
        for (int q = 0; q < 4; q++) {
            float2 g0 = __half22float2(a0[q]);
            float2 g1 = __half22float2(a1[q]);
            float2 g2 = __half22float2(a2[q]);
            float2 g3 = __half22float2(a3[q]);
            acc[q * 2 + 0] += g0.x * w0 + g1.x * w1 + g2.x * w2 + g3.x * w3;
            acc[q * 2 + 1] += g0.y * w0 + g1.y * w1 + g2.y * w2 + g3.y * w3;
        }
        e0 = f0; e1 = f1; e2 = f2n; e3 = f3;
        i = j;
    }
    for (; i < end; i++) {
        int2 eo = g_edge[i];
        float w0 = __int_as_float(eo.y);
        uint4 v0 = tv[(size_t)eo.x * RS + c8];
        const __half2* a0 = (const __half2*)&v0;
#pragma unroll
        for (int q = 0; q < 4; q++) {
            float2 g0 = __half22float2(a0[q]);
            acc[q * 2 + 0] += g0.x * w0;
            acc[q * 2 + 1] += g0.y * w0;
        }
    }
    __half h[8];
#pragma unroll
    for (int q = 0; q < 8; q++) {
        float u = acc[q] > 0.f ? acc[q] : 0.01f * acc[q];
        h[q] = __float2half(u);
    }
    *(uint4*)(hs + (size_t)node * F + c8 * 8) = *(uint4*)h;
}

template<int F, int NPB>
__global__ __launch_bounds__(128) void csr_agg_proj(const float* __restrict__ t,
                                                    const float* __restrict__ b,
                                                    const float* __restrict__ Wp,
                                                    const float* __restrict__ bp,
                                                    float* __restrict__ out) {
    constexpr int C = F / 4;
    int node = blockIdx.x * NPB + threadIdx.x / C;
    int ch = threadIdx.x % C;
    if (node >= N_NODES) return;
    int beg = g_rp[node], end = g_rp[node + 1];
    const float4* tv = (const float4*)t;
    float d = g_dinv[node];
    float dd = d * d;
    float4 self = tv[(size_t)node * C + ch];
    float4 bv = ((const float4*)b)[ch];
    float4 acc = make_float4(fmaf(self.x, dd, bv.x), fmaf(self.y, dd, bv.y),
                             fmaf(self.z, dd, bv.z), fmaf(self.w, dd, bv.w));
    int stop = beg + ((end - beg) & ~3);
    int i = beg;
    int2 e0, e1, e2, e3;
    if (i < stop) {
        e0 = g_edge[i]; e1 = g_edge[i + 1]; e2 = g_edge[i + 2]; e3 = g_edge[i + 3];
    }
    while (i < stop) {
        int j = i + 4;
        int2 f0, f1, f2n, f3;
        if (j < stop) {
            f0 = g_edge[j]; f1 = g_edge[j + 1]; f2n = g_edge[j + 2]; f3 = g_edge[j + 3];
        }
        float4 v0 = tv[(size_t)e0.x * C + ch];
        float4 v1 = tv[(size_t)e1.x * C + ch];
        float4 v2 = tv[(size_t)e2.x * C + ch];
        float4 v3 = tv[(size_t)e3.x * C + ch];
        float w0 = __int_as_float(e0.y), w1 = __int_as_float(e1.y);
        float w2 = __int_as_float(e2.y), w3 = __int_as_float(e3.y);
        acc.x += v0.x * w0 + v1.x * w1 + v2.x * w2 + v3.x * w3;
        acc.y += v0.y * w0 + v1.y * w1 + v2.y * w2 + v3.y * w3;
        acc.z += v0.z * w0 + v1.z * w1 + v2.z * w2 + v3.z * w3;
        acc.w += v0.w * w0 + v1.w * w1 + v2.w * w2 + v3.w * w3;
        e0 = f0; e1 = f1; e2 = f2n; e3 = f3;
        i = j;
    }
    for (; i < end; i++) {
        int2 eo = g_edge[i];
        float w0 = __int_as_float(eo.y);
        float4 v0 = tv[(size_t)eo.x * C + ch];
        acc.x += v0.x * w0; acc.y += v0.y * w0; acc.z += v0.z * w0; acc.w += v0.w * w0;
    }
    float f[4] = {acc.x, acc.y, acc.z, acc.w};
#pragma unroll
    for (int q = 0; q < 4; q++) f[q] = f[q] > 0.f ? f[q] : 0.01f * f[q];
    float a0 = 0.f, a1 = 0.f, a2 = 0.f;
#pragma unroll
    for (int q = 0; q < 4; q++) {
        int k = ch * 4 + q;
        a0 = fmaf(f[q], __ldg(Wp + k * 3 + 0), a0);
        a1 = fmaf(f[q], __ldg(Wp + k * 3 + 1), a1);
        a2 = fmaf(f[q], __ldg(Wp + k * 3 + 2), a2);
    }
#pragma unroll
    for (int off = C / 2; off; off >>= 1) {
        a0 += __shfl_down_sync(0xffffffffu, a0, off, C);
        a1 += __shfl_down_sync(0xffffffffu, a1, off, C);
        a2 += __shfl_down_sync(0xffffffffu, a2, off, C);
    }
    if (ch == 0) {
        out[(size_t)node * 3 + 0] = a0 + bp[0];
        out[(size_t)node * 3 + 1] = a1 + bp[1];
        out[(size_t)node * 3 + 2] = a2 + bp[2];
    }
}

// ======================= launch =======================
extern "C" void kernel_launch(void* const* d_in, const int* in_sizes, int n_in,
                              void* d_out, int out_size) {
    const float* x           = (const float*)d_in[0];
    const int*   edge_index  = (const int*)  d_in[1];
    const float* edge_attr   = (const float*)d_in[2];
    const float* layer_table = (const float*)d_in[3];
    const float* rel_table   = (const float*)d_in[4];
    const float* color_table = (const float*)d_in[5];
    const float* W1 = (const float*)d_in[6];
    const float* b1 = (const float*)d_in[7];
    const float* W2 = (const float*)d_in[8];
    const float* b2 = (const float*)d_in[9];
    const float* W3 = (const float*)d_in[10];
    const float* b3 = (const float*)d_in[11];
    const float* Wp = (const float*)d_in[12];
    const float* bp = (const float*)d_in[13];
    float* out = (float*)d_out;

    __half *p_A2, *p_h2s, *p_h3s, *p_W1T, *p_W2T, *p_W3T, *p_base;
    float *p_t;
    cudaGetSymbolAddress((void**)&p_A2,   g_A2);
    cudaGetSymbolAddress((void**)&p_h2s,  g_h2s);
    cudaGetSymbolAddress((void**)&p_h3s,  g_h3s);
    cudaGetSymbolAddress((void**)&p_W1T,  g_W1T);
    cudaGetSymbolAddress((void**)&p_W2T,  g_W2T);
    cudaGetSymbolAddress((void**)&p_W3T,  g_W3T);
    cudaGetSymbolAddress((void**)&p_base, g_base);
    cudaGetSymbolAddress((void**)&p_t,    g_t);
    __half* p_th = (__half*)p_t;

    const int T = 256;
    const int SM128 = 3 * (128 + 128) * 128;   // 98304
    const int SM64  = 3 * (128 + 64) * 128;    // 73728
    cudaFuncSetAttribute((const void*)mma_gemm<128, true,  true>,  cudaFuncAttributeMaxDynamicSharedMemorySize, SM128);
    cudaFuncSetAttribute((const void*)mma_gemm<128, false, true>,  cudaFuncAttributeMaxDynamicSharedMemorySize, SM128);
    cudaFuncSetAttribute((const void*)mma_gemm<64,  false, false>, cudaFuncAttributeMaxDynamicSharedMemorySize, SM64);

    // Side stream + events: parallel graph branches under capture.
    cudaStream_t s2;
    cudaStreamCreateWithFlags(&s2, cudaStreamNonBlocking);
    cudaEvent_t evFork, evG1a, evA1a, evG2a, evA2a;
    cudaEventCreateWithFlags(&evFork, cudaEventDisableTiming);
    cudaEventCreateWithFlags(&evG1a,  cudaEventDisableTiming);
    cudaEventCreateWithFlags(&evA1a,  cudaEventDisableTiming);
    cudaEventCreateWithFlags(&evG2a,  cudaEventDisableTiming);
    cudaEventCreateWithFlags(&evA2a,  cudaEventDisableTiming);

    cudaEventRecord(evFork, 0);
    cudaStreamWaitEvent(s2, evFork, 0);

    // ---- side branch: CSR build ----
    zero_both<<<(N_NODES + T - 1) / T, T, 0, s2>>>();
    deg_kernel<<<(N_EDGES + T - 1) / T, T, 0, s2>>>(edge_index, edge_attr);
    scan_kernel<<<1, 1024, 0, s2>>>();
    scatter_kernel<<<(N_EDGES + T - 1) / T, T, 0, s2>>>(edge_index, edge_attr);

    // ---- main branch: GEMM inputs ----
    convW<<<(W1N + W2N + W3N + T - 1) / T, T>>>(W1, W2, W3);
    pre_all<<<782, 512>>>(layer_table, rel_table, color_table, W1);
    split_base<<<N_NODES, T>>>(x);

    const int MT = (N_NODES + 127) / 128;   // 157

    // ======== layer 1: 2-way split-N pipeline (256 / 256 cols) ========
    mma_gemm<128, true, true><<<dim3(2, MT), T, SM128>>>(p_A2, p_W1T, p_base, p_th, N_NODES, KP1, F1, 0);
    cudaEventRecord(evG1a, 0);
    mma_gemm<128, true, true><<<dim3(2, MT), T, SM128>>>(p_A2, p_W1T, p_base, p_th, N_NODES, KP1, F1, 256);

    cudaStreamWaitEvent(s2, evG1a, 0);   // s2 already ordered after CSR build
    csr_agg_h<F1, 256, 4><<<(N_NODES + 3) / 4, 128, 0, s2>>>(p_th, b1, p_h2s, 0);
    cudaEventRecord(evA1a, s2);

    cudaStreamWaitEvent(0, evA1a, 0);    // orders CSR + agg1a before main's agg1b
    csr_agg_h<F1, 256, 4><<<(N_NODES + 3) / 4, 128>>>(p_th, b1, p_h2s, 256);

    // ======== layer 2: split-N pipeline (agg writes g_h3s — no aliasing with g_h2s input) ========
    mma_gemm<128, false, true><<<dim3(1, MT), T, SM128>>>(p_h2s, p_W2T, nullptr, p_th, N_NODES, F1, F2, 0);
    cudaEventRecord(evG2a, 0);
    mma_gemm<128, false, true><<<dim3(1, MT), T, SM128>>>(p_h2s, p_W2T, nullptr, p_th, N_NODES, F1, F2, 128);

    cudaStreamWaitEvent(s2, evG2a, 0);
    csr_agg_h<F2, 128, 8><<<(N_NODES + 7) / 8, 128, 0, s2>>>(p_th, b2, p_h3s, 0);
    cudaEventRecord(evA2a, s2);

    cudaStreamWaitEvent(0, evA2a, 0);
    csr_agg_h<F2, 128, 8><<<(N_NODES + 7) / 8, 128>>>(p_th, b2, p_h3s, 128);

    // ======== layer 3 (serial, projection fused; reads g_h3s) ========
    mma_gemm<64, false, false><<<dim3(1, MT), T, SM64>>>(p_h3s, p_W3T, nullptr, p_t, N_NODES, F2, F3, 0);
    csr_agg_proj<F3, 8><<<(N_NODES + 7) / 8, 128>>>(p_t, b3, Wp, bp, out);
}